// round 3
// baseline (speedup 1.0000x reference)
#include <cuda_runtime.h>
#include <cuda_bf16.h>
#include <cstdint>

#define NPTS_MAX 100000
#define CDIM 64
#define HEADS 8
#define HDIM 8
#define KNN 16
#define WARPS_PER_BLOCK 8

// Scratch for K/V projections (25.6 MB each) — static device globals (no alloc).
__device__ float g_k[(size_t)NPTS_MAX * CDIM];
__device__ float g_v[(size_t)NPTS_MAX * CDIM];

// ---------------------------------------------------------------------------
// Kernel A: k = feats @ Wk, v = feats @ Wv   (one warp per point)
// ---------------------------------------------------------------------------
__global__ __launch_bounds__(256) void proj_kv_kernel(
    const float* __restrict__ feats,
    const float* __restrict__ Wk,
    const float* __restrict__ Wv,
    int n_pts)
{
    __shared__ float Wk_s[CDIM * CDIM];
    __shared__ float Wv_s[CDIM * CDIM];
    __shared__ float fs[WARPS_PER_BLOCK][CDIM];

    const int tid = threadIdx.x;
    for (int i = tid; i < CDIM * CDIM; i += 256) {
        Wk_s[i] = Wk[i];
        Wv_s[i] = Wv[i];
    }
    __syncthreads();

    const int wid  = tid >> 5;
    const int lane = tid & 31;
    const int n = blockIdx.x * WARPS_PER_BLOCK + wid;
    if (n >= n_pts) return;

    const float* frow = feats + (size_t)n * CDIM;
    fs[wid][lane]      = frow[lane];
    fs[wid][lane + 32] = frow[lane + 32];
    __syncwarp();

    float k0 = 0.f, k1 = 0.f, v0 = 0.f, v1 = 0.f;
#pragma unroll
    for (int i = 0; i < CDIM; i++) {
        const float f = fs[wid][i];
        k0 = fmaf(f, Wk_s[i * CDIM + lane],      k0);
        k1 = fmaf(f, Wk_s[i * CDIM + 32 + lane], k1);
        v0 = fmaf(f, Wv_s[i * CDIM + lane],      v0);
        v1 = fmaf(f, Wv_s[i * CDIM + 32 + lane], v1);
    }
    float* krow = g_k + (size_t)n * CDIM;
    float* vrow = g_v + (size_t)n * CDIM;
    krow[lane]      = k0;
    krow[lane + 32] = k1;
    vrow[lane]      = v0;
    vrow[lane + 32] = v1;
}

// ---------------------------------------------------------------------------
// Kernel B: q projection + KNN gather attention + output projection
// One warp per point.
//   - q: each lane produces 2 of the 64 q values (pre-scaled by 1/sqrt(D))
//   - scores: 2 lanes per neighbor (lane/2 = nb, lane&1 = half), each lane
//     covers 4 heads; softmax over the 16 neighbors via xor-shuffle (masks
//     2,4,8,16 keep the lane-parity group intact)
//   - out accumulation: fully coalesced v reads (lane = channel)
//   - final: out @ Wo + bo with Wo in SMEM
// ---------------------------------------------------------------------------
__global__ __launch_bounds__(256) void attn_kernel(
    const float* __restrict__ feats,
    const int*   __restrict__ knn,
    const float* __restrict__ Wq,
    const float* __restrict__ Wo,
    const float* __restrict__ bo,
    float*       __restrict__ out,
    int n_pts)
{
    __shared__ float Wq_s[CDIM * CDIM];
    __shared__ float Wo_s[CDIM * CDIM];
    __shared__ float bo_s[CDIM];
    __shared__ float fs[WARPS_PER_BLOCK][CDIM];      // feats row, reused as out vec
    __shared__ float qs[WARPS_PER_BLOCK][CDIM];      // q (pre-scaled)
    __shared__ float attn_s[WARPS_PER_BLOCK][KNN * HEADS];
    __shared__ int   idx_s[WARPS_PER_BLOCK][KNN];

    const int tid = threadIdx.x;
    for (int i = tid; i < CDIM * CDIM; i += 256) {
        Wq_s[i] = Wq[i];
        Wo_s[i] = Wo[i];
    }
    if (tid < CDIM) bo_s[tid] = bo[tid];
    __syncthreads();

    const int wid  = tid >> 5;
    const int lane = tid & 31;
    const int n = blockIdx.x * WARPS_PER_BLOCK + wid;
    if (n >= n_pts) return;

    // ---- load feats row ----
    const float* frow = feats + (size_t)n * CDIM;
    fs[wid][lane]      = frow[lane];
    fs[wid][lane + 32] = frow[lane + 32];
    __syncwarp();

    // ---- q = feats @ Wq, scaled by 1/sqrt(D) ----
    const float scale = 0.3535533905932738f;  // 1/sqrt(8)
    float q0 = 0.f, q1 = 0.f;
#pragma unroll
    for (int i = 0; i < CDIM; i++) {
        const float f = fs[wid][i];
        q0 = fmaf(f, Wq_s[i * CDIM + lane],      q0);
        q1 = fmaf(f, Wq_s[i * CDIM + 32 + lane], q1);
    }
    qs[wid][lane]      = q0 * scale;
    qs[wid][lane + 32] = q1 * scale;
    __syncwarp();

    // ---- scores: lane -> (nb = lane/2, half = lane&1), 4 heads per lane ----
    const int nb   = lane >> 1;
    const int half = lane & 1;
    const int idx  = knn[n * KNN + nb];
    if (half == 0) idx_s[wid][nb] = idx;

    float kv[32];
    {
        const float4* kp = reinterpret_cast<const float4*>(
            g_k + (size_t)idx * CDIM + half * 32);
#pragma unroll
        for (int t = 0; t < 8; t++) {
            const float4 r = kp[t];
            kv[4 * t + 0] = r.x;
            kv[4 * t + 1] = r.y;
            kv[4 * t + 2] = r.z;
            kv[4 * t + 3] = r.w;
        }
    }

    const int hbase = half * 4;
    float s[4];
#pragma unroll
    for (int j = 0; j < 4; j++) {
        float acc = 0.f;
#pragma unroll
        for (int d = 0; d < HDIM; d++)
            acc = fmaf(qs[wid][(hbase + j) * HDIM + d], kv[j * HDIM + d], acc);
        s[j] = acc;
    }

    // ---- softmax over the 16 neighbors (lanes of equal parity) ----
#pragma unroll
    for (int j = 0; j < 4; j++) {
        float m = s[j];
        m = fmaxf(m, __shfl_xor_sync(0xffffffffu, m, 2));
        m = fmaxf(m, __shfl_xor_sync(0xffffffffu, m, 4));
        m = fmaxf(m, __shfl_xor_sync(0xffffffffu, m, 8));
        m = fmaxf(m, __shfl_xor_sync(0xffffffffu, m, 16));
        const float e = __expf(s[j] - m);
        float sum = e;
        sum += __shfl_xor_sync(0xffffffffu, sum, 2);
        sum += __shfl_xor_sync(0xffffffffu, sum, 4);
        sum += __shfl_xor_sync(0xffffffffu, sum, 8);
        sum += __shfl_xor_sync(0xffffffffu, sum, 16);
        attn_s[wid][nb * HEADS + hbase + j] = e / sum;
    }
    __syncwarp();

    // ---- out[h,d] = sum_nb attn[nb,h] * v[nb, h*8+d]  (coalesced v reads) ----
    const int h0 = lane >> 3;          // channel c = lane      -> head c/8
    const int h1 = (lane + 32) >> 3;   // channel c = lane + 32 -> head c/8
    float o0 = 0.f, o1 = 0.f;
#pragma unroll
    for (int t = 0; t < KNN; t++) {
        const int id = idx_s[wid][t];
        const float* vp = g_v + (size_t)id * CDIM;
        o0 = fmaf(attn_s[wid][t * HEADS + h0], vp[lane],      o0);
        o1 = fmaf(attn_s[wid][t * HEADS + h1], vp[lane + 32], o1);
    }
    fs[wid][lane]      = o0;   // reuse feats buffer for out vector
    fs[wid][lane + 32] = o1;
    __syncwarp();

    // ---- final: y = out @ Wo + bo ----
    float y0 = bo_s[lane];
    float y1 = bo_s[lane + 32];
#pragma unroll
    for (int i = 0; i < CDIM; i++) {
        const float f = fs[wid][i];
        y0 = fmaf(f, Wo_s[i * CDIM + lane],      y0);
        y1 = fmaf(f, Wo_s[i * CDIM + 32 + lane], y1);
    }
    float* orow = out + (size_t)n * CDIM;
    orow[lane]      = y0;
    orow[lane + 32] = y1;
}

// ---------------------------------------------------------------------------
// Launch
// ---------------------------------------------------------------------------
extern "C" void kernel_launch(void* const* d_in, const int* in_sizes, int n_in,
                              void* d_out, int out_size)
{
    const float* feats = (const float*)d_in[0];
    const int*   knn   = (const int*)  d_in[1];
    const float* Wq    = (const float*)d_in[2];
    const float* Wk    = (const float*)d_in[3];
    const float* Wv    = (const float*)d_in[4];
    const float* Wo    = (const float*)d_in[5];
    const float* bo    = (const float*)d_in[6];
    float* out = (float*)d_out;

    const int n_pts = in_sizes[0] / CDIM;   // 100000
    const int grid  = (n_pts + WARPS_PER_BLOCK - 1) / WARPS_PER_BLOCK;

    proj_kv_kernel<<<grid, 256>>>(feats, Wk, Wv, n_pts);
    attn_kernel<<<grid, 256>>>(feats, knn, Wq, Wo, bo, out, n_pts);
}

// round 5
// speedup vs baseline: 1.6920x; 1.6920x over previous
#include <cuda_runtime.h>
#include <cuda_bf16.h>
#include <cstdint>

#define NPTS_MAX 100000
#define CDIM 64
#define HEADS 8
#define HDIM 8
#define KNN 16
#define WPB 8          // warps per block
#define P 4            // points per warp (register blocking)
#define PTS_PER_BLOCK (WPB * P)

// Scratch for K/V projections (25.6 MB each) — static device globals (no alloc).
__device__ float g_k[(size_t)NPTS_MAX * CDIM];
__device__ float g_v[(size_t)NPTS_MAX * CDIM];

// Extract component j (compile-time after unroll) from a float4.
__device__ __forceinline__ float f4_get(const float4& f, int j) {
    return j == 0 ? f.x : (j == 1 ? f.y : (j == 2 ? f.z : f.w));
}

// ---------------------------------------------------------------------------
// Kernel A: k = feats @ Wk, v = feats @ Wv   (one warp per P points)
// ---------------------------------------------------------------------------
__global__ __launch_bounds__(256) void proj_kv_kernel(
    const float* __restrict__ feats,
    const float* __restrict__ Wk,
    const float* __restrict__ Wv,
    int n_pts)
{
    __shared__ float Wk_s[CDIM * CDIM];
    __shared__ float Wv_s[CDIM * CDIM];
    __shared__ __align__(16) float fs[WPB][P * CDIM];

    const int tid = threadIdx.x;
    for (int i = tid; i < CDIM * CDIM; i += 256) {
        Wk_s[i] = Wk[i];
        Wv_s[i] = Wv[i];
    }
    __syncthreads();

    const int wid  = tid >> 5;
    const int lane = tid & 31;
    const int n0 = (blockIdx.x * WPB + wid) * P;

#pragma unroll
    for (int p = 0; p < P; p++) {
        const int n = n0 + p;
        if (n < n_pts) {
            const float* fr = feats + (size_t)n * CDIM;
            fs[wid][p * CDIM + lane]      = fr[lane];
            fs[wid][p * CDIM + lane + 32] = fr[lane + 32];
        }
    }
    __syncwarp();

    float k0[P], k1[P], v0[P], v1[P];
#pragma unroll
    for (int p = 0; p < P; p++) { k0[p] = k1[p] = v0[p] = v1[p] = 0.f; }

    for (int i = 0; i < CDIM; i += 4) {
        float4 f[P];
#pragma unroll
        for (int p = 0; p < P; p++)
            f[p] = *reinterpret_cast<const float4*>(&fs[wid][p * CDIM + i]);
#pragma unroll
        for (int j = 0; j < 4; j++) {
            const float wk0 = Wk_s[(i + j) * CDIM + lane];
            const float wk1 = Wk_s[(i + j) * CDIM + 32 + lane];
            const float wv0 = Wv_s[(i + j) * CDIM + lane];
            const float wv1 = Wv_s[(i + j) * CDIM + 32 + lane];
#pragma unroll
            for (int p = 0; p < P; p++) {
                const float fv = f4_get(f[p], j);
                k0[p] = fmaf(fv, wk0, k0[p]);
                k1[p] = fmaf(fv, wk1, k1[p]);
                v0[p] = fmaf(fv, wv0, v0[p]);
                v1[p] = fmaf(fv, wv1, v1[p]);
            }
        }
    }

#pragma unroll
    for (int p = 0; p < P; p++) {
        const int n = n0 + p;
        if (n < n_pts) {
            float* krow = g_k + (size_t)n * CDIM;
            float* vrow = g_v + (size_t)n * CDIM;
            krow[lane]      = k0[p];
            krow[lane + 32] = k1[p];
            vrow[lane]      = v0[p];
            vrow[lane + 32] = v1[p];
        }
    }
}

// ---------------------------------------------------------------------------
// Kernel B: q projection + KNN gather attention + output projection
// One warp per P points. Buffer reuse: fs holds feats -> q (scaled) -> out vec.
// ---------------------------------------------------------------------------
__global__ __launch_bounds__(256) void attn_kernel(
    const float* __restrict__ feats,
    const int*   __restrict__ knn,
    const float* __restrict__ Wq,
    const float* __restrict__ Wo,
    const float* __restrict__ bo,
    float*       __restrict__ out,
    int n_pts)
{
    __shared__ float Wq_s[CDIM * CDIM];
    __shared__ float Wo_s[CDIM * CDIM];
    __shared__ float bo_s[CDIM];
    __shared__ __align__(16) float fs[WPB][P * CDIM];   // feats -> q -> out vec
    __shared__ float attn_s[WPB][KNN * HEADS];           // one point at a time
    __shared__ int   idx_s[WPB][KNN];

    const int tid = threadIdx.x;
    for (int i = tid; i < CDIM * CDIM; i += 256) {
        Wq_s[i] = Wq[i];
        Wo_s[i] = Wo[i];
    }
    if (tid < CDIM) bo_s[tid] = bo[tid];
    __syncthreads();

    const int wid  = tid >> 5;
    const int lane = tid & 31;
    const int n0 = (blockIdx.x * WPB + wid) * P;

    // ---- load feats rows for P points ----
#pragma unroll
    for (int p = 0; p < P; p++) {
        const int n = n0 + p;
        if (n < n_pts) {
            const float* fr = feats + (size_t)n * CDIM;
            fs[wid][p * CDIM + lane]      = fr[lane];
            fs[wid][p * CDIM + lane + 32] = fr[lane + 32];
        }
    }
    __syncwarp();

    // ---- q = feats @ Wq (accumulate in regs, then overwrite fs with q*scale) ----
    const float scale = 0.3535533905932738f;  // 1/sqrt(8)
    float q0[P], q1[P];
#pragma unroll
    for (int p = 0; p < P; p++) { q0[p] = q1[p] = 0.f; }

    for (int i = 0; i < CDIM; i += 4) {
        float4 f[P];
#pragma unroll
        for (int p = 0; p < P; p++)
            f[p] = *reinterpret_cast<const float4*>(&fs[wid][p * CDIM + i]);
#pragma unroll
        for (int j = 0; j < 4; j++) {
            const float w0 = Wq_s[(i + j) * CDIM + lane];
            const float w1 = Wq_s[(i + j) * CDIM + 32 + lane];
#pragma unroll
            for (int p = 0; p < P; p++) {
                const float fv = f4_get(f[p], j);
                q0[p] = fmaf(fv, w0, q0[p]);
                q1[p] = fmaf(fv, w1, q1[p]);
            }
        }
    }
    __syncwarp();   // all lanes done reading feats from fs
#pragma unroll
    for (int p = 0; p < P; p++) {
        fs[wid][p * CDIM + lane]      = q0[p] * scale;
        fs[wid][p * CDIM + lane + 32] = q1[p] * scale;
    }
    __syncwarp();

    // ---- per-point gather + softmax + v accumulation ----
    const int nb   = lane >> 1;
    const int half = lane & 1;
    const int hbase = half * 4;
    const int h0 = lane >> 3;
    const int h1 = (lane + 32) >> 3;

#pragma unroll
    for (int p = 0; p < P; p++) {
        const int n = n0 + p;
        if (n < n_pts) {
            const int idx = knn[(size_t)n * KNN + nb];
            if (half == 0) idx_s[wid][nb] = idx;

            // gather 32 k-values (4 heads x 8 dims) for this lane's (nb, half)
            float kv[32];
            {
                const float4* kp = reinterpret_cast<const float4*>(
                    g_k + (size_t)idx * CDIM + half * 32);
#pragma unroll
                for (int t = 0; t < 8; t++) {
                    const float4 r = kp[t];
                    kv[4 * t + 0] = r.x;
                    kv[4 * t + 1] = r.y;
                    kv[4 * t + 2] = r.z;
                    kv[4 * t + 3] = r.w;
                }
            }

            // scores for 4 heads (q already scaled)
            float s[4];
#pragma unroll
            for (int j = 0; j < 4; j++) {
                const float4 qa = *reinterpret_cast<const float4*>(
                    &fs[wid][p * CDIM + (hbase + j) * HDIM]);
                const float4 qb = *reinterpret_cast<const float4*>(
                    &fs[wid][p * CDIM + (hbase + j) * HDIM + 4]);
                float acc;
                acc = qa.x * kv[j * 8 + 0];
                acc = fmaf(qa.y, kv[j * 8 + 1], acc);
                acc = fmaf(qa.z, kv[j * 8 + 2], acc);
                acc = fmaf(qa.w, kv[j * 8 + 3], acc);
                acc = fmaf(qb.x, kv[j * 8 + 4], acc);
                acc = fmaf(qb.y, kv[j * 8 + 5], acc);
                acc = fmaf(qb.z, kv[j * 8 + 6], acc);
                acc = fmaf(qb.w, kv[j * 8 + 7], acc);
                s[j] = acc;
            }

            // softmax over the 16 neighbors (xor masks 2/4/8/16 keep parity group)
#pragma unroll
            for (int j = 0; j < 4; j++) {
                float m = s[j];
                m = fmaxf(m, __shfl_xor_sync(0xffffffffu, m, 2));
                m = fmaxf(m, __shfl_xor_sync(0xffffffffu, m, 4));
                m = fmaxf(m, __shfl_xor_sync(0xffffffffu, m, 8));
                m = fmaxf(m, __shfl_xor_sync(0xffffffffu, m, 16));
                const float e = __expf(s[j] - m);
                float sum = e;
                sum += __shfl_xor_sync(0xffffffffu, sum, 2);
                sum += __shfl_xor_sync(0xffffffffu, sum, 4);
                sum += __shfl_xor_sync(0xffffffffu, sum, 8);
                sum += __shfl_xor_sync(0xffffffffu, sum, 16);
                attn_s[wid][nb * HEADS + hbase + j] = e / sum;
            }
            __syncwarp();

            // out[c] = sum_t attn[t, c/8] * v[t, c]   (coalesced v reads)
            float o0 = 0.f, o1 = 0.f;
#pragma unroll
            for (int t = 0; t < KNN; t++) {
                const int id = idx_s[wid][t];
                const float* vp = g_v + (size_t)id * CDIM;
                o0 = fmaf(attn_s[wid][t * HEADS + h0], vp[lane],      o0);
                o1 = fmaf(attn_s[wid][t * HEADS + h1], vp[lane + 32], o1);
            }
            __syncwarp();   // done reading q (fs) & attn_s for this point
            fs[wid][p * CDIM + lane]      = o0;   // overwrite q with out vector
            fs[wid][p * CDIM + lane + 32] = o1;
        }
        __syncwarp();       // attn_s / idx_s reuse across points
    }

    // ---- final: y = outvec @ Wo + bo ----
    float y0[P], y1[P];
#pragma unroll
    for (int p = 0; p < P; p++) { y0[p] = bo_s[lane]; y1[p] = bo_s[lane + 32]; }

    for (int i = 0; i < CDIM; i += 4) {
        float4 f[P];
#pragma unroll
        for (int p = 0; p < P; p++)
            f[p] = *reinterpret_cast<const float4*>(&fs[wid][p * CDIM + i]);
#pragma unroll
        for (int j = 0; j < 4; j++) {
            const float w0 = Wo_s[(i + j) * CDIM + lane];
            const float w1 = Wo_s[(i + j) * CDIM + 32 + lane];
#pragma unroll
            for (int p = 0; p < P; p++) {
                const float fv = f4_get(f[p], j);
                y0[p] = fmaf(fv, w0, y0[p]);
                y1[p] = fmaf(fv, w1, y1[p]);
            }
        }
    }

#pragma unroll
    for (int p = 0; p < P; p++) {
        const int n = n0 + p;
        if (n < n_pts) {
            float* orow = out + (size_t)n * CDIM;
            orow[lane]      = y0[p];
            orow[lane + 32] = y1[p];
        }
    }
}

// ---------------------------------------------------------------------------
// Launch
// ---------------------------------------------------------------------------
extern "C" void kernel_launch(void* const* d_in, const int* in_sizes, int n_in,
                              void* d_out, int out_size)
{
    const float* feats = (const float*)d_in[0];
    const int*   knn   = (const int*)  d_in[1];
    const float* Wq    = (const float*)d_in[2];
    const float* Wk    = (const float*)d_in[3];
    const float* Wv    = (const float*)d_in[4];
    const float* Wo    = (const float*)d_in[5];
    const float* bo    = (const float*)d_in[6];
    float* out = (float*)d_out;

    const int n_pts = in_sizes[0] / CDIM;   // 100000
    const int grid  = (n_pts + PTS_PER_BLOCK - 1) / PTS_PER_BLOCK;

    proj_kv_kernel<<<grid, 256>>>(feats, Wk, Wv, n_pts);
    attn_kernel<<<grid, 256>>>(feats, knn, Wq, Wo, bo, out, n_pts);
}

// round 7
// speedup vs baseline: 2.1729x; 1.2842x over previous
#include <cuda_runtime.h>
#include <cuda_bf16.h>
#include <cstdint>

#define NPTS_MAX 100000
#define CDIM 64
#define HEADS 8
#define HDIM 8
#define KNN 16
#define TSTRIDE 20   // padded stride of attnT rows (conflict-free banks, 16B-alignable)

// ---- proj kernel geometry ----
#define WPB_A 4        // warps per block (proj)
#define P_A 8          // points per warp (proj)
// ---- attn kernel geometry ----
#define WPB_B 4        // warps per block (attn)
#define P_B 4          // points per warp (attn)

// Scratch for K/V projections (25.6 MB each) — static device globals (no alloc).
__device__ float g_k[(size_t)NPTS_MAX * CDIM];
__device__ float g_v[(size_t)NPTS_MAX * CDIM];

__device__ __forceinline__ float f4_get(const float4& f, int j) {
    return j == 0 ? f.x : (j == 1 ? f.y : (j == 2 ? f.z : f.w));
}

// ---------------------------------------------------------------------------
// Kernel A: k = feats @ Wk, v = feats @ Wv   (one warp per P_A points)
// ---------------------------------------------------------------------------
__global__ __launch_bounds__(WPB_A * 32) void proj_kv_kernel(
    const float* __restrict__ feats,
    const float* __restrict__ Wk,
    const float* __restrict__ Wv,
    int n_pts)
{
    __shared__ float Wk_s[CDIM * CDIM];
    __shared__ float Wv_s[CDIM * CDIM];
    __shared__ __align__(16) float fs[WPB_A][P_A * CDIM];

    const int tid = threadIdx.x;
    for (int i = tid; i < CDIM * CDIM; i += WPB_A * 32) {
        Wk_s[i] = Wk[i];
        Wv_s[i] = Wv[i];
    }
    __syncthreads();

    const int wid  = tid >> 5;
    const int lane = tid & 31;
    const int n0 = (blockIdx.x * WPB_A + wid) * P_A;

#pragma unroll
    for (int p = 0; p < P_A; p++) {
        const int n = n0 + p;
        if (n < n_pts) {
            const float* fr = feats + (size_t)n * CDIM;
            fs[wid][p * CDIM + lane]      = fr[lane];
            fs[wid][p * CDIM + lane + 32] = fr[lane + 32];
        }
    }
    __syncwarp();

    float k0[P_A], k1[P_A], v0[P_A], v1[P_A];
#pragma unroll
    for (int p = 0; p < P_A; p++) { k0[p] = k1[p] = v0[p] = v1[p] = 0.f; }

    for (int i = 0; i < CDIM; i += 4) {
        float4 f[P_A];
#pragma unroll
        for (int p = 0; p < P_A; p++)
            f[p] = *reinterpret_cast<const float4*>(&fs[wid][p * CDIM + i]);
#pragma unroll
        for (int j = 0; j < 4; j++) {
            const float wk0 = Wk_s[(i + j) * CDIM + lane];
            const float wk1 = Wk_s[(i + j) * CDIM + 32 + lane];
            const float wv0 = Wv_s[(i + j) * CDIM + lane];
            const float wv1 = Wv_s[(i + j) * CDIM + 32 + lane];
#pragma unroll
            for (int p = 0; p < P_A; p++) {
                const float fv = f4_get(f[p], j);
                k0[p] = fmaf(fv, wk0, k0[p]);
                k1[p] = fmaf(fv, wk1, k1[p]);
                v0[p] = fmaf(fv, wv0, v0[p]);
                v1[p] = fmaf(fv, wv1, v1[p]);
            }
        }
    }

#pragma unroll
    for (int p = 0; p < P_A; p++) {
        const int n = n0 + p;
        if (n < n_pts) {
            float* krow = g_k + (size_t)n * CDIM;
            float* vrow = g_v + (size_t)n * CDIM;
            krow[lane]      = k0[p];
            krow[lane + 32] = k1[p];
            vrow[lane]      = v0[p];
            vrow[lane + 32] = v1[p];
        }
    }
}

// ---------------------------------------------------------------------------
// Kernel B: q projection + KNN gather attention + output projection
// One warp per P_B points.
//   k-gather: lane = (r = lane>>3 line-slot, e = lane&7 16B-chunk); each
//   LDG.128 covers 4 full 128B lines (8 lanes each) -> 4 wavefronts/instr.
//   half = r&1, head = 4*half + e>>1 are per-lane constants.
//   Scores -> attnT[h][t] (stride 20, conflict-free), shuffle softmax,
//   broadcast-float4 attn reads in the coalesced v phase.
// ---------------------------------------------------------------------------
__global__ __launch_bounds__(WPB_B * 32) void attn_kernel(
    const float* __restrict__ feats,
    const int*   __restrict__ knn,
    const float* __restrict__ Wq,
    const float* __restrict__ Wo,
    const float* __restrict__ bo,
    float*       __restrict__ out,
    int n_pts)
{
    __shared__ float Wq_s[CDIM * CDIM];
    __shared__ float Wo_s[CDIM * CDIM];
    __shared__ float bo_s[CDIM];
    __shared__ __align__(16) float fs[WPB_B][P_B * CDIM];        // feats -> q -> out vec
    __shared__ __align__(16) float attnT[WPB_B][HEADS * TSTRIDE]; // scores/attn, [h][t]

    const int tid = threadIdx.x;
    for (int i = tid; i < CDIM * CDIM; i += WPB_B * 32) {
        Wq_s[i] = Wq[i];
        Wo_s[i] = Wo[i];
    }
    if (tid < CDIM) bo_s[tid] = bo[tid];
    __syncthreads();

    const int wid  = tid >> 5;
    const int lane = tid & 31;
    const int n0 = (blockIdx.x * WPB_B + wid) * P_B;

    // ---- load feats rows for P_B points ----
#pragma unroll
    for (int p = 0; p < P_B; p++) {
        const int n = n0 + p;
        if (n < n_pts) {
            const float* fr = feats + (size_t)n * CDIM;
            fs[wid][p * CDIM + lane]      = fr[lane];
            fs[wid][p * CDIM + lane + 32] = fr[lane + 32];
        }
    }
    __syncwarp();

    // ---- q = feats @ Wq -> regs -> fs (scaled) ----
    const float scale = 0.3535533905932738f;  // 1/sqrt(8)
    float q0[P_B], q1[P_B];
#pragma unroll
    for (int p = 0; p < P_B; p++) { q0[p] = q1[p] = 0.f; }

    for (int i = 0; i < CDIM; i += 4) {
        float4 f[P_B];
#pragma unroll
        for (int p = 0; p < P_B; p++)
            f[p] = *reinterpret_cast<const float4*>(&fs[wid][p * CDIM + i]);
#pragma unroll
        for (int j = 0; j < 4; j++) {
            const float w0 = Wq_s[(i + j) * CDIM + lane];
            const float w1 = Wq_s[(i + j) * CDIM + 32 + lane];
#pragma unroll
            for (int p = 0; p < P_B; p++) {
                const float fv = f4_get(f[p], j);
                q0[p] = fmaf(fv, w0, q0[p]);
                q1[p] = fmaf(fv, w1, q1[p]);
            }
        }
    }
    __syncwarp();
#pragma unroll
    for (int p = 0; p < P_B; p++) {
        fs[wid][p * CDIM + lane]      = q0[p] * scale;
        fs[wid][p * CDIM + lane + 32] = q1[p] * scale;
    }
    __syncwarp();

    // per-lane constants for gather / score
    const int r       = lane >> 3;       // line slot 0..3
    const int e       = lane & 7;        // 16B chunk within 128B line
    const int half_r  = r & 1;           // which 32-channel half this lane gathers
    const int rowoff  = r >> 1;          // row parity
    const int head_g  = 4 * half_r + (e >> 1);   // head this lane's chunk belongs to
    // softmax constants (lane = (nb, half))
    const int nb    = lane >> 1;
    const int half  = lane & 1;
    const int hbase = half * 4;
    // v-phase constants (lane = channel)
    const int h0 = lane >> 3;
    const int h1 = 4 + (lane >> 3);

#pragma unroll
    for (int p = 0; p < P_B; p++) {
        const int n = n0 + p;
        if (n < n_pts) {
            int my_idx = 0;
            if (lane < KNN) my_idx = knn[(size_t)n * KNN + lane];

            // q chunks this lane needs (channels 4e..4e+3 of each half)
            const float4 qA = *reinterpret_cast<const float4*>(&fs[wid][p * CDIM + 4 * e]);
            const float4 qB = *reinterpret_cast<const float4*>(&fs[wid][p * CDIM + 32 + 4 * e]);
            const float4 q4 = half_r ? qB : qA;

            // ---- cooperative-line k gather: 8 x LDG.128, 4 lines per instr ----
            int   ids[8];
#pragma unroll
            for (int i = 0; i < 8; i++)
                ids[i] = __shfl_sync(0xffffffffu, my_idx, 2 * i + rowoff);

            float4 k4[8];
#pragma unroll
            for (int i = 0; i < 8; i++)
                k4[i] = *reinterpret_cast<const float4*>(
                    g_k + (size_t)ids[i] * CDIM + half_r * 32 + e * 4);

#pragma unroll
            for (int i = 0; i < 8; i++) {
                float pp = q4.x * k4[i].x;
                pp = fmaf(q4.y, k4[i].y, pp);
                pp = fmaf(q4.z, k4[i].z, pp);
                pp = fmaf(q4.w, k4[i].w, pp);
                pp += __shfl_xor_sync(0xffffffffu, pp, 1);   // join d0-3 + d4-7
                if ((e & 1) == 0)
                    attnT[wid][head_g * TSTRIDE + 2 * i + rowoff] = pp;
            }
            __syncwarp();

            // ---- softmax over 16 neighbors (xor 2/4/8/16 keeps half-parity group) ----
#pragma unroll
            for (int j = 0; j < 4; j++) {
                const int slot = (hbase + j) * TSTRIDE + nb;
                float s = attnT[wid][slot];
                float m = s;
                m = fmaxf(m, __shfl_xor_sync(0xffffffffu, m, 2));
                m = fmaxf(m, __shfl_xor_sync(0xffffffffu, m, 4));
                m = fmaxf(m, __shfl_xor_sync(0xffffffffu, m, 8));
                m = fmaxf(m, __shfl_xor_sync(0xffffffffu, m, 16));
                const float ex = __expf(s - m);
                float sum = ex;
                sum += __shfl_xor_sync(0xffffffffu, sum, 2);
                sum += __shfl_xor_sync(0xffffffffu, sum, 4);
                sum += __shfl_xor_sync(0xffffffffu, sum, 8);
                sum += __shfl_xor_sync(0xffffffffu, sum, 16);
                attnT[wid][slot] = ex / sum;
            }
            __syncwarp();

            // ---- out[c] = sum_t attn[h(c), t] * v[t, c]  (coalesced v reads) ----
            float o0 = 0.f, o1 = 0.f;
#pragma unroll
            for (int tt = 0; tt < 4; tt++) {
                const float4 a0 = *reinterpret_cast<const float4*>(
                    &attnT[wid][h0 * TSTRIDE + tt * 4]);
                const float4 a1 = *reinterpret_cast<const float4*>(
                    &attnT[wid][h1 * TSTRIDE + tt * 4]);
#pragma unroll
                for (int u = 0; u < 4; u++) {
                    const int id = __shfl_sync(0xffffffffu, my_idx, tt * 4 + u);
                    const float* vp = g_v + (size_t)id * CDIM;
                    o0 = fmaf(f4_get(a0, u), vp[lane],      o0);
                    o1 = fmaf(f4_get(a1, u), vp[lane + 32], o1);
                }
            }
            __syncwarp();   // done with attnT & q for this point
            fs[wid][p * CDIM + lane]      = o0;   // overwrite q with out vector
            fs[wid][p * CDIM + lane + 32] = o1;
        }
        __syncwarp();       // attnT reuse across points
    }

    // ---- final: y = outvec @ Wo + bo ----
    float y0[P_B], y1[P_B];
#pragma unroll
    for (int p = 0; p < P_B; p++) { y0[p] = bo_s[lane]; y1[p] = bo_s[lane + 32]; }

    for (int i = 0; i < CDIM; i += 4) {
        float4 f[P_B];
#pragma unroll
        for (int p = 0; p < P_B; p++)
            f[p] = *reinterpret_cast<const float4*>(&fs[wid][p * CDIM + i]);
#pragma unroll
        for (int j = 0; j < 4; j++) {
            const float w0 = Wo_s[(i + j) * CDIM + lane];
            const float w1 = Wo_s[(i + j) * CDIM + 32 + lane];
#pragma unroll
            for (int p = 0; p < P_B; p++) {
                const float fv = f4_get(f[p], j);
                y0[p] = fmaf(fv, w0, y0[p]);
                y1[p] = fmaf(fv, w1, y1[p]);
            }
        }
    }

#pragma unroll
    for (int p = 0; p < P_B; p++) {
        const int n = n0 + p;
        if (n < n_pts) {
            float* orow = out + (size_t)n * CDIM;
            orow[lane]      = y0[p];
            orow[lane + 32] = y1[p];
        }
    }
}

// ---------------------------------------------------------------------------
// Launch
// ---------------------------------------------------------------------------
extern "C" void kernel_launch(void* const* d_in, const int* in_sizes, int n_in,
                              void* d_out, int out_size)
{
    const float* feats = (const float*)d_in[0];
    const int*   knn   = (const int*)  d_in[1];
    const float* Wq    = (const float*)d_in[2];
    const float* Wk    = (const float*)d_in[3];
    const float* Wv    = (const float*)d_in[4];
    const float* Wo    = (const float*)d_in[5];
    const float* bo    = (const float*)d_in[6];
    float* out = (float*)d_out;

    const int n_pts = in_sizes[0] / CDIM;   // 100000

    const int ptsA = WPB_A * P_A;           // 32
    const int ptsB = WPB_B * P_B;           // 16
    const int gridA = (n_pts + ptsA - 1) / ptsA;
    const int gridB = (n_pts + ptsB - 1) / ptsB;

    proj_kv_kernel<<<gridA, WPB_A * 32>>>(feats, Wk, Wv, n_pts);
    attn_kernel<<<gridB, WPB_B * 32>>>(feats, knn, Wq, Wo, bo, out, n_pts);
}

// round 9
// speedup vs baseline: 2.6379x; 1.2140x over previous
#include <cuda_runtime.h>
#include <cuda_fp16.h>
#include <cstdint>

#define NPTS_MAX 100000
#define CDIM 64
#define HEADS 8
#define KNN 16
#define TSTRIDE 20    // attnT row stride (floats): conflict-free + 16B-aligned
#define WSTRIDE 68    // transposed-weight row stride (floats): conflict-free LDS.128

// ---- proj kernel geometry ----
#define WPB_A 4        // warps per block
#define P_A 8          // points per warp
// ---- attn kernel geometry ----
#define WPB_B 4
#define P_B 8

// K/V projection scratch in fp16 (12.8 MB each) — static device globals.
__device__ __half g_k16[(size_t)NPTS_MAX * CDIM];
__device__ __half g_v16[(size_t)NPTS_MAX * CDIM];

__device__ __forceinline__ float f4_get(const float4& f, int j) {
    return j == 0 ? f.x : (j == 1 ? f.y : (j == 2 ? f.z : f.w));
}

// ---------------------------------------------------------------------------
// Kernel A: k = feats @ Wk, v = feats @ Wv  -> fp16 scratch
// One warp per P_A points; weights transposed in SMEM (stride 68, LDS.128).
// ---------------------------------------------------------------------------
__global__ __launch_bounds__(WPB_A * 32) void proj_kv_kernel(
    const float* __restrict__ feats,
    const float* __restrict__ Wk,
    const float* __restrict__ Wv,
    int n_pts)
{
    __shared__ __align__(16) float Wk_t[CDIM * WSTRIDE];
    __shared__ __align__(16) float Wv_t[CDIM * WSTRIDE];
    __shared__ __align__(16) float fs[WPB_A][P_A * CDIM];

    const int tid = threadIdx.x;
    for (int i = tid; i < CDIM * CDIM; i += WPB_A * 32) {
        const int row = i >> 6, col = i & 63;
        Wk_t[col * WSTRIDE + row] = Wk[i];
        Wv_t[col * WSTRIDE + row] = Wv[i];
    }
    __syncthreads();

    const int wid  = tid >> 5;
    const int lane = tid & 31;
    const int n0 = (blockIdx.x * WPB_A + wid) * P_A;

#pragma unroll
    for (int p = 0; p < P_A; p++) {
        const int n = n0 + p;
        if (n < n_pts) {
            const float* fr = feats + (size_t)n * CDIM;
            fs[wid][p * CDIM + lane]      = fr[lane];
            fs[wid][p * CDIM + lane + 32] = fr[lane + 32];
        }
    }
    __syncwarp();

    float k0[P_A], k1[P_A], v0[P_A], v1[P_A];
#pragma unroll
    for (int p = 0; p < P_A; p++) { k0[p] = k1[p] = v0[p] = v1[p] = 0.f; }

    for (int i = 0; i < CDIM; i += 4) {
        float4 f[P_A];
#pragma unroll
        for (int p = 0; p < P_A; p++)
            f[p] = *reinterpret_cast<const float4*>(&fs[wid][p * CDIM + i]);
        const float4 wk0 = *reinterpret_cast<const float4*>(&Wk_t[lane * WSTRIDE + i]);
        const float4 wk1 = *reinterpret_cast<const float4*>(&Wk_t[(lane + 32) * WSTRIDE + i]);
        const float4 wv0 = *reinterpret_cast<const float4*>(&Wv_t[lane * WSTRIDE + i]);
        const float4 wv1 = *reinterpret_cast<const float4*>(&Wv_t[(lane + 32) * WSTRIDE + i]);
#pragma unroll
        for (int j = 0; j < 4; j++) {
#pragma unroll
            for (int p = 0; p < P_A; p++) {
                const float fv = f4_get(f[p], j);
                k0[p] = fmaf(fv, f4_get(wk0, j), k0[p]);
                k1[p] = fmaf(fv, f4_get(wk1, j), k1[p]);
                v0[p] = fmaf(fv, f4_get(wv0, j), v0[p]);
                v1[p] = fmaf(fv, f4_get(wv1, j), v1[p]);
            }
        }
    }

#pragma unroll
    for (int p = 0; p < P_A; p++) {
        const int n = n0 + p;
        if (n < n_pts) {
            __half* krow = g_k16 + (size_t)n * CDIM;
            __half* vrow = g_v16 + (size_t)n * CDIM;
            krow[lane]      = __float2half(k0[p]);
            krow[lane + 32] = __float2half(k1[p]);
            vrow[lane]      = __float2half(v0[p]);
            vrow[lane + 32] = __float2half(v1[p]);
        }
    }
}

// ---------------------------------------------------------------------------
// Kernel B: q projection + KNN gather attention + output projection.
// One warp per P_B points.
//   - Weight tile W_t holds Wq during phase 1, overwritten with Wo after a
//     block barrier (halves weight SMEM).
//   - k-gather (fp16 rows = 128B): lane=(r=lane>>3 row-slot, e=lane&7 head);
//     each LDG.128 covers 4 full lines; lane's 16B chunk = full head e ->
//     direct dot8, no shuffle join. 4 instr, 16 wf/point.
//   - v-gather: lane = channel pair, half2 loads, 16 wf/point.
// ---------------------------------------------------------------------------
__global__ __launch_bounds__(WPB_B * 32) void attn_kernel(
    const float* __restrict__ feats,
    const int*   __restrict__ knn,
    const float* __restrict__ Wq,
    const float* __restrict__ Wo,
    const float* __restrict__ bo,
    float*       __restrict__ out,
    int n_pts)
{
    __shared__ __align__(16) float W_t[CDIM * WSTRIDE];   // Wq -> Wo
    __shared__ float bo_s[CDIM];
    __shared__ __align__(16) float fs[WPB_B][P_B * CDIM];       // feats -> q -> out vec
    __shared__ __align__(16) float attnT[WPB_B][HEADS * TSTRIDE];

    const int tid = threadIdx.x;
    for (int i = tid; i < CDIM * CDIM; i += WPB_B * 32) {
        const int row = i >> 6, col = i & 63;
        W_t[col * WSTRIDE + row] = Wq[i];
    }
    __syncthreads();

    const int wid  = tid >> 5;
    const int lane = tid & 31;
    const int n0 = (blockIdx.x * WPB_B + wid) * P_B;

    // ---- load feats rows ----
#pragma unroll
    for (int p = 0; p < P_B; p++) {
        const int n = n0 + p;
        if (n < n_pts) {
            const float* fr = feats + (size_t)n * CDIM;
            fs[wid][p * CDIM + lane]      = fr[lane];
            fs[wid][p * CDIM + lane + 32] = fr[lane + 32];
        }
    }
    __syncwarp();

    // ---- q = feats @ Wq -> fs (scaled) ----
    const float scale = 0.3535533905932738f;  // 1/sqrt(8)
    float q0[P_B], q1[P_B];
#pragma unroll
    for (int p = 0; p < P_B; p++) { q0[p] = q1[p] = 0.f; }

    for (int i = 0; i < CDIM; i += 4) {
        float4 f[P_B];
#pragma unroll
        for (int p = 0; p < P_B; p++)
            f[p] = *reinterpret_cast<const float4*>(&fs[wid][p * CDIM + i]);
        const float4 w0 = *reinterpret_cast<const float4*>(&W_t[lane * WSTRIDE + i]);
        const float4 w1 = *reinterpret_cast<const float4*>(&W_t[(lane + 32) * WSTRIDE + i]);
#pragma unroll
        for (int j = 0; j < 4; j++) {
#pragma unroll
            for (int p = 0; p < P_B; p++) {
                const float fv = f4_get(f[p], j);
                q0[p] = fmaf(fv, f4_get(w0, j), q0[p]);
                q1[p] = fmaf(fv, f4_get(w1, j), q1[p]);
            }
        }
    }
    __syncwarp();
#pragma unroll
    for (int p = 0; p < P_B; p++) {
        fs[wid][p * CDIM + lane]      = q0[p] * scale;
        fs[wid][p * CDIM + lane + 32] = q1[p] * scale;
    }

    // ---- swap weight tile: Wq -> Wo ----
    __syncthreads();
    for (int i = tid; i < CDIM * CDIM; i += WPB_B * 32) {
        const int row = i >> 6, col = i & 63;
        W_t[col * WSTRIDE + row] = Wo[i];
    }
    if (tid < CDIM) bo_s[tid] = bo[tid];
    __syncthreads();

    // per-lane constants
    const int r = lane >> 3;            // k-gather: row slot 0..3
    const int e = lane & 7;             // k-gather: head / 16B chunk
    const int nb   = lane >> 1;         // softmax: neighbor
    const int half = lane & 1;          // softmax: head group
    const int hbase = half * 4;
    const int hv = lane >> 2;           // v-phase: head of channel pair `lane`

#pragma unroll
    for (int p = 0; p < P_B; p++) {
        const int n = n0 + p;
        if (n < n_pts) {
            int my_idx = 0;
            if (lane < KNN) my_idx = knn[(size_t)n * KNN + lane];

            // q for head e (channels 8e..8e+7), pre-scaled
            const float4 qa = *reinterpret_cast<const float4*>(&fs[wid][p * CDIM + 8 * e]);
            const float4 qb = *reinterpret_cast<const float4*>(&fs[wid][p * CDIM + 8 * e + 4]);

            // ---- k gather: 4 x LDG.128, each covers 4 fp16 rows ----
            int ids[4];
#pragma unroll
            for (int i4 = 0; i4 < 4; i4++)
                ids[i4] = __shfl_sync(0xffffffffu, my_idx, 4 * i4 + r);
            uint4 raw[4];
#pragma unroll
            for (int i4 = 0; i4 < 4; i4++)
                raw[i4] = *reinterpret_cast<const uint4*>(
                    g_k16 + (size_t)ids[i4] * CDIM + e * 8);

#pragma unroll
            for (int i4 = 0; i4 < 4; i4++) {
                const float2 c0 = __half22float2(*reinterpret_cast<const __half2*>(&raw[i4].x));
                const float2 c1 = __half22float2(*reinterpret_cast<const __half2*>(&raw[i4].y));
                const float2 c2 = __half22float2(*reinterpret_cast<const __half2*>(&raw[i4].z));
                const float2 c3 = __half22float2(*reinterpret_cast<const __half2*>(&raw[i4].w));
                float acc = qa.x * c0.x;
                acc = fmaf(qa.y, c0.y, acc);
                acc = fmaf(qa.z, c1.x, acc);
                acc = fmaf(qa.w, c1.y, acc);
                acc = fmaf(qb.x, c2.x, acc);
                acc = fmaf(qb.y, c2.y, acc);
                acc = fmaf(qb.z, c3.x, acc);
                acc = fmaf(qb.w, c3.y, acc);
                attnT[wid][e * TSTRIDE + 4 * i4 + r] = acc;
            }
            __syncwarp();

            // ---- softmax over 16 neighbors (xor 2/4/8/16 keeps parity group) ----
#pragma unroll
            for (int j = 0; j < 4; j++) {
                const int slot = (hbase + j) * TSTRIDE + nb;
                const float s = attnT[wid][slot];
                float m = s;
                m = fmaxf(m, __shfl_xor_sync(0xffffffffu, m, 2));
                m = fmaxf(m, __shfl_xor_sync(0xffffffffu, m, 4));
                m = fmaxf(m, __shfl_xor_sync(0xffffffffu, m, 8));
                m = fmaxf(m, __shfl_xor_sync(0xffffffffu, m, 16));
                const float ex = __expf(s - m);
                float sum = ex;
                sum += __shfl_xor_sync(0xffffffffu, sum, 2);
                sum += __shfl_xor_sync(0xffffffffu, sum, 4);
                sum += __shfl_xor_sync(0xffffffffu, sum, 8);
                sum += __shfl_xor_sync(0xffffffffu, sum, 16);
                attnT[wid][slot] = ex / sum;
            }
            __syncwarp();

            // ---- out pair (2*lane, 2*lane+1) = sum_t attn[hv,t] * v[t,pair] ----
            float o0 = 0.f, o1 = 0.f;
#pragma unroll
            for (int tt = 0; tt < 4; tt++) {
                const float4 a = *reinterpret_cast<const float4*>(
                    &attnT[wid][hv * TSTRIDE + 4 * tt]);
#pragma unroll
                for (int u = 0; u < 4; u++) {
                    const int id = __shfl_sync(0xffffffffu, my_idx, 4 * tt + u);
                    const __half2 vh = reinterpret_cast<const __half2*>(
                        g_v16 + (size_t)id * CDIM)[lane];
                    const float2 vf = __half22float2(vh);
                    const float aw = f4_get(a, u);
                    o0 = fmaf(aw, vf.x, o0);
                    o1 = fmaf(aw, vf.y, o1);
                }
            }
            __syncwarp();   // done reading q (fs) & attnT for this point
            reinterpret_cast<float2*>(&fs[wid][p * CDIM])[lane] = make_float2(o0, o1);
        }
        __syncwarp();       // attnT reuse across points
    }
    __syncwarp();

    // ---- final: y = outvec @ Wo + bo ----
    float y0[P_B], y1[P_B];
#pragma unroll
    for (int p = 0; p < P_B; p++) { y0[p] = bo_s[lane]; y1[p] = bo_s[lane + 32]; }

    for (int i = 0; i < CDIM; i += 4) {
        float4 f[P_B];
#pragma unroll
        for (int p = 0; p < P_B; p++)
            f[p] = *reinterpret_cast<const float4*>(&fs[wid][p * CDIM + i]);
        const float4 w0 = *reinterpret_cast<const float4*>(&W_t[lane * WSTRIDE + i]);
        const float4 w1 = *reinterpret_cast<const float4*>(&W_t[(lane + 32) * WSTRIDE + i]);
#pragma unroll
        for (int j = 0; j < 4; j++) {
#pragma unroll
            for (int p = 0; p < P_B; p++) {
                const float fv = f4_get(f[p], j);
                y0[p] = fmaf(fv, f4_get(w0, j), y0[p]);
                y1[p] = fmaf(fv, f4_get(w1, j), y1[p]);
            }
        }
    }

#pragma unroll
    for (int p = 0; p < P_B; p++) {
        const int n = n0 + p;
        if (n < n_pts) {
            float* orow = out + (size_t)n * CDIM;
            orow[lane]      = y0[p];
            orow[lane + 32] = y1[p];
        }
    }
}

// ---------------------------------------------------------------------------
// Launch
// ---------------------------------------------------------------------------
extern "C" void kernel_launch(void* const* d_in, const int* in_sizes, int n_in,
                              void* d_out, int out_size)
{
    const float* feats = (const float*)d_in[0];
    const int*   knn   = (const int*)  d_in[1];
    const float* Wq    = (const float*)d_in[2];
    const float* Wk    = (const float*)d_in[3];
    const float* Wv    = (const float*)d_in[4];
    const float* Wo    = (const float*)d_in[5];
    const float* bo    = (const float*)d_in[6];
    float* out = (float*)d_out;

    const int n_pts = in_sizes[0] / CDIM;   // 100000

    const int ptsA = WPB_A * P_A;           // 32
    const int ptsB = WPB_B * P_B;           // 32
    const int gridA = (n_pts + ptsA - 1) / ptsA;
    const int gridB = (n_pts + ptsB - 1) / ptsB;

    proj_kv_kernel<<<gridA, WPB_A * 32>>>(feats, Wk, Wv, n_pts);
    attn_kernel<<<gridB, WPB_B * 32>>>(feats, knn, Wq, Wo, bo, out, n_pts);
}

// round 10
// speedup vs baseline: 2.8364x; 1.0752x over previous
#include <cuda_runtime.h>
#include <cuda_fp16.h>
#include <cstdint>

#define NPTS_MAX 100000
#define CDIM 64
#define HEADS 8
#define KNN 16
#define TSTRIDE 20    // attnT row stride (floats)
#define WSTRIDE 68    // transposed-weight row stride (floats): conflict-free LDS.128

// ---- proj kernel geometry ----
#define WPB_A 4        // warps per block
#define P_A 8          // points per warp
// ---- attn kernel geometry ----
#define WPB_B 4
#define P_B 8

// Scratch (static device globals — no alloc):
//   k,v in fp16 (12.8 MB each), q pre-scaled in fp32 (25.6 MB).
__device__ __half g_k16[(size_t)NPTS_MAX * CDIM];
__device__ __half g_v16[(size_t)NPTS_MAX * CDIM];
__device__ float  g_q  [(size_t)NPTS_MAX * CDIM];

__device__ __forceinline__ float f4_get(const float4& f, int j) {
    return j == 0 ? f.x : (j == 1 ? f.y : (j == 2 ? f.z : f.w));
}

// ---------------------------------------------------------------------------
// Kernel A: k = feats @ Wk, v = feats @ Wv  -> fp16 scratch
//           q = (feats @ Wq) * 1/sqrt(8)   -> fp32 scratch (phase 2, tile swap)
// One warp per P_A points; weights transposed in SMEM (stride 68, LDS.128).
// ---------------------------------------------------------------------------
__global__ __launch_bounds__(WPB_A * 32) void proj_qkv_kernel(
    const float* __restrict__ feats,
    const float* __restrict__ Wq,
    const float* __restrict__ Wk,
    const float* __restrict__ Wv,
    int n_pts)
{
    __shared__ __align__(16) float Wk_t[CDIM * WSTRIDE];   // Wk -> Wq (phase 2)
    __shared__ __align__(16) float Wv_t[CDIM * WSTRIDE];
    __shared__ __align__(16) float fs[WPB_A][P_A * CDIM];

    const int tid = threadIdx.x;
    for (int i = tid; i < CDIM * CDIM; i += WPB_A * 32) {
        const int row = i >> 6, col = i & 63;
        Wk_t[col * WSTRIDE + row] = Wk[i];
        Wv_t[col * WSTRIDE + row] = Wv[i];
    }
    __syncthreads();

    const int wid  = tid >> 5;
    const int lane = tid & 31;
    const int n0 = (blockIdx.x * WPB_A + wid) * P_A;

#pragma unroll
    for (int p = 0; p < P_A; p++) {
        const int n = n0 + p;
        if (n < n_pts) {
            const float* fr = feats + (size_t)n * CDIM;
            fs[wid][p * CDIM + lane]      = fr[lane];
            fs[wid][p * CDIM + lane + 32] = fr[lane + 32];
        }
    }
    __syncwarp();

    // ---- phase 1: k and v ----
    {
        float k0[P_A], k1[P_A], v0[P_A], v1[P_A];
#pragma unroll
        for (int p = 0; p < P_A; p++) { k0[p] = k1[p] = v0[p] = v1[p] = 0.f; }

        for (int i = 0; i < CDIM; i += 4) {
            float4 f[P_A];
#pragma unroll
            for (int p = 0; p < P_A; p++)
                f[p] = *reinterpret_cast<const float4*>(&fs[wid][p * CDIM + i]);
            const float4 wk0 = *reinterpret_cast<const float4*>(&Wk_t[lane * WSTRIDE + i]);
            const float4 wk1 = *reinterpret_cast<const float4*>(&Wk_t[(lane + 32) * WSTRIDE + i]);
            const float4 wv0 = *reinterpret_cast<const float4*>(&Wv_t[lane * WSTRIDE + i]);
            const float4 wv1 = *reinterpret_cast<const float4*>(&Wv_t[(lane + 32) * WSTRIDE + i]);
#pragma unroll
            for (int j = 0; j < 4; j++) {
#pragma unroll
                for (int p = 0; p < P_A; p++) {
                    const float fv = f4_get(f[p], j);
                    k0[p] = fmaf(fv, f4_get(wk0, j), k0[p]);
                    k1[p] = fmaf(fv, f4_get(wk1, j), k1[p]);
                    v0[p] = fmaf(fv, f4_get(wv0, j), v0[p]);
                    v1[p] = fmaf(fv, f4_get(wv1, j), v1[p]);
                }
            }
        }

#pragma unroll
        for (int p = 0; p < P_A; p++) {
            const int n = n0 + p;
            if (n < n_pts) {
                __half* krow = g_k16 + (size_t)n * CDIM;
                __half* vrow = g_v16 + (size_t)n * CDIM;
                krow[lane]      = __float2half(k0[p]);
                krow[lane + 32] = __float2half(k1[p]);
                vrow[lane]      = __float2half(v0[p]);
                vrow[lane + 32] = __float2half(v1[p]);
            }
        }
    }

    // ---- swap Wk tile -> Wq ----
    __syncthreads();
    for (int i = tid; i < CDIM * CDIM; i += WPB_A * 32) {
        const int row = i >> 6, col = i & 63;
        Wk_t[col * WSTRIDE + row] = Wq[i];
    }
    __syncthreads();

    // ---- phase 2: q (pre-scaled, fp32) ----
    {
        const float scale = 0.3535533905932738f;  // 1/sqrt(8)
        float q0[P_A], q1[P_A];
#pragma unroll
        for (int p = 0; p < P_A; p++) { q0[p] = q1[p] = 0.f; }

        for (int i = 0; i < CDIM; i += 4) {
            float4 f[P_A];
#pragma unroll
            for (int p = 0; p < P_A; p++)
                f[p] = *reinterpret_cast<const float4*>(&fs[wid][p * CDIM + i]);
            const float4 w0 = *reinterpret_cast<const float4*>(&Wk_t[lane * WSTRIDE + i]);
            const float4 w1 = *reinterpret_cast<const float4*>(&Wk_t[(lane + 32) * WSTRIDE + i]);
#pragma unroll
            for (int j = 0; j < 4; j++) {
#pragma unroll
                for (int p = 0; p < P_A; p++) {
                    const float fv = f4_get(f[p], j);
                    q0[p] = fmaf(fv, f4_get(w0, j), q0[p]);
                    q1[p] = fmaf(fv, f4_get(w1, j), q1[p]);
                }
            }
        }

#pragma unroll
        for (int p = 0; p < P_A; p++) {
            const int n = n0 + p;
            if (n < n_pts) {
                float* qrow = g_q + (size_t)n * CDIM;
                qrow[lane]      = q0[p] * scale;
                qrow[lane + 32] = q1[p] * scale;
            }
        }
    }
}

// ---------------------------------------------------------------------------
// Kernel B: KNN gather attention + output projection.
// One warp per P_B points. q read from scratch (fp32, pre-scaled).
//   k-gather: lane=(r=lane>>3 row-slot, e=lane&7 head); 4 LDG.128 cover
//     16 fp16 rows; lane's 16B chunk = full head e -> direct dot8.
//   softmax: lane=(h=lane>>2, qt=lane&3): LDS.128 of 4 scores, in-register
//     reduce + xor 1,2 shuffles only.
//   v-gather: lane = channel pair, half2 loads, coalesced.
//   o-GEMM: Wo transposed in SMEM, out vectors staged in fs.
// ---------------------------------------------------------------------------
__global__ __launch_bounds__(WPB_B * 32) void attn_kernel(
    const int*   __restrict__ knn,
    const float* __restrict__ Wo,
    const float* __restrict__ bo,
    float*       __restrict__ out,
    int n_pts)
{
    __shared__ __align__(16) float W_t[CDIM * WSTRIDE];          // Wo only
    __shared__ float bo_s[CDIM];
    __shared__ __align__(16) float fs[WPB_B][P_B * CDIM];        // out vectors
    __shared__ __align__(16) float attnT[WPB_B][HEADS * TSTRIDE];

    const int tid = threadIdx.x;
    for (int i = tid; i < CDIM * CDIM; i += WPB_B * 32) {
        const int row = i >> 6, col = i & 63;
        W_t[col * WSTRIDE + row] = Wo[i];
    }
    if (tid < CDIM) bo_s[tid] = bo[tid];
    __syncthreads();

    const int wid  = tid >> 5;
    const int lane = tid & 31;
    const int n0 = (blockIdx.x * WPB_B + wid) * P_B;

    // per-lane constants
    const int r  = lane >> 3;           // k-gather: row slot 0..3
    const int e  = lane & 7;            // k-gather: head / 16B chunk
    const int hs = lane >> 2;           // softmax: head
    const int qt = lane & 3;            // softmax: quarter
    const int hv = lane >> 2;           // v-phase: head of channel pair `lane`

#pragma unroll
    for (int p = 0; p < P_B; p++) {
        const int n = n0 + p;
        if (n < n_pts) {
            int my_idx = 0;
            if (lane < KNN) my_idx = knn[(size_t)n * KNN + lane];

            // q for head e (channels 8e..8e+7), pre-scaled fp32 from scratch
            const float* qrow = g_q + (size_t)n * CDIM;
            const float4 qa = *reinterpret_cast<const float4*>(qrow + 8 * e);
            const float4 qb = *reinterpret_cast<const float4*>(qrow + 8 * e + 4);

            // ---- k gather: 4 x LDG.128, each covers 4 fp16 rows ----
            int ids[4];
#pragma unroll
            for (int i4 = 0; i4 < 4; i4++)
                ids[i4] = __shfl_sync(0xffffffffu, my_idx, 4 * i4 + r);
            uint4 raw[4];
#pragma unroll
            for (int i4 = 0; i4 < 4; i4++)
                raw[i4] = *reinterpret_cast<const uint4*>(
                    g_k16 + (size_t)ids[i4] * CDIM + e * 8);

#pragma unroll
            for (int i4 = 0; i4 < 4; i4++) {
                const float2 c0 = __half22float2(*reinterpret_cast<const __half2*>(&raw[i4].x));
                const float2 c1 = __half22float2(*reinterpret_cast<const __half2*>(&raw[i4].y));
                const float2 c2 = __half22float2(*reinterpret_cast<const __half2*>(&raw[i4].z));
                const float2 c3 = __half22float2(*reinterpret_cast<const __half2*>(&raw[i4].w));
                float acc = qa.x * c0.x;
                acc = fmaf(qa.y, c0.y, acc);
                acc = fmaf(qa.z, c1.x, acc);
                acc = fmaf(qa.w, c1.y, acc);
                acc = fmaf(qb.x, c2.x, acc);
                acc = fmaf(qb.y, c2.y, acc);
                acc = fmaf(qb.z, c3.x, acc);
                acc = fmaf(qb.w, c3.y, acc);
                attnT[wid][e * TSTRIDE + 4 * i4 + r] = acc;
            }
            __syncwarp();

            // ---- softmax: lane = (head hs, quarter qt); 4 scores per lane ----
            {
                float4 s4 = *reinterpret_cast<const float4*>(
                    &attnT[wid][hs * TSTRIDE + 4 * qt]);
                float m = fmaxf(fmaxf(s4.x, s4.y), fmaxf(s4.z, s4.w));
                m = fmaxf(m, __shfl_xor_sync(0xffffffffu, m, 1));
                m = fmaxf(m, __shfl_xor_sync(0xffffffffu, m, 2));
                const float e0 = __expf(s4.x - m);
                const float e1 = __expf(s4.y - m);
                const float e2 = __expf(s4.z - m);
                const float e3 = __expf(s4.w - m);
                float sum = (e0 + e1) + (e2 + e3);
                sum += __shfl_xor_sync(0xffffffffu, sum, 1);
                sum += __shfl_xor_sync(0xffffffffu, sum, 2);
                const float inv = __frcp_rn(sum);
                *reinterpret_cast<float4*>(&attnT[wid][hs * TSTRIDE + 4 * qt]) =
                    make_float4(e0 * inv, e1 * inv, e2 * inv, e3 * inv);
            }
            __syncwarp();

            // ---- out pair (2*lane, 2*lane+1) = sum_t attn[hv,t] * v[t,pair] ----
            float o0 = 0.f, o1 = 0.f;
#pragma unroll
            for (int tt = 0; tt < 4; tt++) {
                const float4 a = *reinterpret_cast<const float4*>(
                    &attnT[wid][hv * TSTRIDE + 4 * tt]);
#pragma unroll
                for (int u = 0; u < 4; u++) {
                    const int id = __shfl_sync(0xffffffffu, my_idx, 4 * tt + u);
                    const __half2 vh = reinterpret_cast<const __half2*>(
                        g_v16 + (size_t)id * CDIM)[lane];
                    const float2 vf = __half22float2(vh);
                    const float aw = f4_get(a, u);
                    o0 = fmaf(aw, vf.x, o0);
                    o1 = fmaf(aw, vf.y, o1);
                }
            }
            __syncwarp();   // done with attnT for this point
            reinterpret_cast<float2*>(&fs[wid][p * CDIM])[lane] = make_float2(o0, o1);
        }
        __syncwarp();       // attnT reuse across points
    }
    __syncwarp();

    // ---- final: y = outvec @ Wo + bo ----
    float y0[P_B], y1[P_B];
#pragma unroll
    for (int p = 0; p < P_B; p++) { y0[p] = bo_s[lane]; y1[p] = bo_s[lane + 32]; }

    for (int i = 0; i < CDIM; i += 4) {
        float4 f[P_B];
#pragma unroll
        for (int p = 0; p < P_B; p++)
            f[p] = *reinterpret_cast<const float4*>(&fs[wid][p * CDIM + i]);
        const float4 w0 = *reinterpret_cast<const float4*>(&W_t[lane * WSTRIDE + i]);
        const float4 w1 = *reinterpret_cast<const float4*>(&W_t[(lane + 32) * WSTRIDE + i]);
#pragma unroll
        for (int j = 0; j < 4; j++) {
#pragma unroll
            for (int p = 0; p < P_B; p++) {
                const float fv = f4_get(f[p], j);
                y0[p] = fmaf(fv, f4_get(w0, j), y0[p]);
                y1[p] = fmaf(fv, f4_get(w1, j), y1[p]);
            }
        }
    }

#pragma unroll
    for (int p = 0; p < P_B; p++) {
        const int n = n0 + p;
        if (n < n_pts) {
            float* orow = out + (size_t)n * CDIM;
            orow[lane]      = y0[p];
            orow[lane + 32] = y1[p];
        }
    }
}

// ---------------------------------------------------------------------------
// Launch
// ---------------------------------------------------------------------------
extern "C" void kernel_launch(void* const* d_in, const int* in_sizes, int n_in,
                              void* d_out, int out_size)
{
    const float* feats = (const float*)d_in[0];
    const int*   knn   = (const int*)  d_in[1];
    const float* Wq    = (const float*)d_in[2];
    const float* Wk    = (const float*)d_in[3];
    const float* Wv    = (const float*)d_in[4];
    const float* Wo    = (const float*)d_in[5];
    const float* bo    = (const float*)d_in[6];
    float* out = (float*)d_out;

    const int n_pts = in_sizes[0] / CDIM;   // 100000

    const int ptsA = WPB_A * P_A;           // 32
    const int ptsB = WPB_B * P_B;           // 32
    const int gridA = (n_pts + ptsA - 1) / ptsA;
    const int gridB = (n_pts + ptsB - 1) / ptsB;

    proj_qkv_kernel<<<gridA, WPB_A * 32>>>(feats, Wq, Wk, Wv, n_pts);
    attn_kernel<<<gridB, WPB_B * 32>>>(knn, Wo, bo, out, n_pts);
}

// round 13
// speedup vs baseline: 3.1265x; 1.1023x over previous
#include <cuda_runtime.h>
#include <cuda_fp16.h>
#include <cstdint>

#define NPTS_MAX 100000
#define CDIM 64
#define HEADS 8
#define KNN 16
#define TSTRIDE 20    // attnT row stride (floats)
#define WSTRIDE 68    // transposed-weight row stride (floats): conflict-free LDS.128

// ---- proj kernel geometry ----
#define WPB_A 4        // warps per block
#define P_A 8          // points per warp
#define NPAIR_A (P_A / 2)
// ---- attn kernel geometry ----
#define WPB_B 4
#define P_B 8
#define NPAIR_B (P_B / 2)

// Scratch (static device globals — no alloc):
//   k,v in fp16 (12.8 MB each), q pre-scaled in fp32 (25.6 MB).
__device__ __half g_k16[(size_t)NPTS_MAX * CDIM];
__device__ __half g_v16[(size_t)NPTS_MAX * CDIM];
__device__ float  g_q  [(size_t)NPTS_MAX * CDIM];

__device__ __forceinline__ float f4_get(const float4& f, int j) {
    return j == 0 ? f.x : (j == 1 ? f.y : (j == 2 ? f.z : f.w));
}

// ---- packed fp32x2 helpers (Blackwell FFMA2) ----
__device__ __forceinline__ uint64_t pack2(float x) {
    uint64_t r;
    asm("mov.b64 %0, {%1, %1};" : "=l"(r) : "f"(x));
    return r;
}
__device__ __forceinline__ void ffma2(uint64_t& d, uint64_t a, uint64_t b) {
    asm("fma.rn.f32x2 %0, %1, %2, %0;" : "+l"(d) : "l"(a), "l"(b));
}
__device__ __forceinline__ float2 unpack2(uint64_t v) {
    float2 f;
    asm("mov.b64 {%0, %1}, %2;" : "=f"(f.x), "=f"(f.y) : "l"(v));
    return f;
}

// ---------------------------------------------------------------------------
// Kernel A: k = feats @ Wk, v = feats @ Wv  -> fp16 scratch
//           q = (feats @ Wq) * 1/sqrt(8)   -> fp32 scratch (phase 2, tile swap)
// One warp per P_A points. Activations pair-interleaved in SMEM so each
// LDS.128 yields two packed f32x2 multiplier operands; GEMM runs on FFMA2.
// ---------------------------------------------------------------------------
__global__ __launch_bounds__(WPB_A * 32) void proj_qkv_kernel(
    const float* __restrict__ feats,
    const float* __restrict__ Wq,
    const float* __restrict__ Wk,
    const float* __restrict__ Wv,
    int n_pts)
{
    __shared__ __align__(16) float Wk_t[CDIM * WSTRIDE];   // Wk -> Wq (phase 2)
    __shared__ __align__(16) float Wv_t[CDIM * WSTRIDE];
    __shared__ __align__(16) float2 fs2[WPB_A][NPAIR_A * CDIM];  // pair-interleaved feats

    const int tid = threadIdx.x;
    for (int i = tid; i < CDIM * CDIM; i += WPB_A * 32) {
        const int row = i >> 6, col = i & 63;
        Wk_t[col * WSTRIDE + row] = Wk[i];
        Wv_t[col * WSTRIDE + row] = Wv[i];
    }
    __syncthreads();

    const int wid  = tid >> 5;
    const int lane = tid & 31;
    const int n0 = (blockIdx.x * WPB_A + wid) * P_A;

    // ---- stage feats, pair-interleaved: fs2[t][i] = (f[2t][i], f[2t+1][i]) ----
#pragma unroll
    for (int p = 0; p < P_A; p++) {
        const int n = n0 + p;
        if (n < n_pts) {
            const float* fr = feats + (size_t)n * CDIM;
            float* dst = reinterpret_cast<float*>(&fs2[wid][(p >> 1) * CDIM]);
            dst[lane * 2 + (p & 1)]        = fr[lane];
            dst[(lane + 32) * 2 + (p & 1)] = fr[lane + 32];
        }
    }
    __syncwarp();

    // ---- phase 1: k and v (packed accumulators per point-pair) ----
    {
        uint64_t K0[NPAIR_A], K1[NPAIR_A], V0[NPAIR_A], V1[NPAIR_A];
#pragma unroll
        for (int t = 0; t < NPAIR_A; t++) { K0[t] = K1[t] = V0[t] = V1[t] = 0ull; }

        for (int i = 0; i < CDIM; i += 4) {
            uint64_t fj[4][NPAIR_A];
#pragma unroll
            for (int t = 0; t < NPAIR_A; t++) {
                const ulonglong2 fA = *reinterpret_cast<const ulonglong2*>(
                    &fs2[wid][t * CDIM + i]);
                const ulonglong2 fB = *reinterpret_cast<const ulonglong2*>(
                    &fs2[wid][t * CDIM + i + 2]);
                fj[0][t] = fA.x; fj[1][t] = fA.y; fj[2][t] = fB.x; fj[3][t] = fB.y;
            }
            const float4 wk0 = *reinterpret_cast<const float4*>(&Wk_t[lane * WSTRIDE + i]);
            const float4 wk1 = *reinterpret_cast<const float4*>(&Wk_t[(lane + 32) * WSTRIDE + i]);
            const float4 wv0 = *reinterpret_cast<const float4*>(&Wv_t[lane * WSTRIDE + i]);
            const float4 wv1 = *reinterpret_cast<const float4*>(&Wv_t[(lane + 32) * WSTRIDE + i]);
#pragma unroll
            for (int j = 0; j < 4; j++) {
                const uint64_t pk0 = pack2(f4_get(wk0, j));
                const uint64_t pk1 = pack2(f4_get(wk1, j));
                const uint64_t pv0 = pack2(f4_get(wv0, j));
                const uint64_t pv1 = pack2(f4_get(wv1, j));
#pragma unroll
                for (int t = 0; t < NPAIR_A; t++) {
                    ffma2(K0[t], fj[j][t], pk0);
                    ffma2(K1[t], fj[j][t], pk1);
                    ffma2(V0[t], fj[j][t], pv0);
                    ffma2(V1[t], fj[j][t], pv1);
                }
            }
        }

#pragma unroll
        for (int t = 0; t < NPAIR_A; t++) {
            const float2 k0 = unpack2(K0[t]), k1 = unpack2(K1[t]);
            const float2 v0 = unpack2(V0[t]), v1 = unpack2(V1[t]);
            const int na = n0 + 2 * t, nb = na + 1;
            if (na < n_pts) {
                __half* krow = g_k16 + (size_t)na * CDIM;
                __half* vrow = g_v16 + (size_t)na * CDIM;
                krow[lane] = __float2half(k0.x); krow[lane + 32] = __float2half(k1.x);
                vrow[lane] = __float2half(v0.x); vrow[lane + 32] = __float2half(v1.x);
            }
            if (nb < n_pts) {
                __half* krow = g_k16 + (size_t)nb * CDIM;
                __half* vrow = g_v16 + (size_t)nb * CDIM;
                krow[lane] = __float2half(k0.y); krow[lane + 32] = __float2half(k1.y);
                vrow[lane] = __float2half(v0.y); vrow[lane + 32] = __float2half(v1.y);
            }
        }
    }

    // ---- swap Wk tile -> Wq ----
    __syncthreads();
    for (int i = tid; i < CDIM * CDIM; i += WPB_A * 32) {
        const int row = i >> 6, col = i & 63;
        Wk_t[col * WSTRIDE + row] = Wq[i];
    }
    __syncthreads();

    // ---- phase 2: q (pre-scaled, fp32) ----
    {
        const float scale = 0.3535533905932738f;  // 1/sqrt(8)
        uint64_t Q0[NPAIR_A], Q1[NPAIR_A];
#pragma unroll
        for (int t = 0; t < NPAIR_A; t++) { Q0[t] = Q1[t] = 0ull; }

        for (int i = 0; i < CDIM; i += 4) {
            uint64_t fj[4][NPAIR_A];
#pragma unroll
            for (int t = 0; t < NPAIR_A; t++) {
                const ulonglong2 fA = *reinterpret_cast<const ulonglong2*>(
                    &fs2[wid][t * CDIM + i]);
                const ulonglong2 fB = *reinterpret_cast<const ulonglong2*>(
                    &fs2[wid][t * CDIM + i + 2]);
                fj[0][t] = fA.x; fj[1][t] = fA.y; fj[2][t] = fB.x; fj[3][t] = fB.y;
            }
            const float4 w0 = *reinterpret_cast<const float4*>(&Wk_t[lane * WSTRIDE + i]);
            const float4 w1 = *reinterpret_cast<const float4*>(&Wk_t[(lane + 32) * WSTRIDE + i]);
#pragma unroll
            for (int j = 0; j < 4; j++) {
                const uint64_t p0 = pack2(f4_get(w0, j));
                const uint64_t p1 = pack2(f4_get(w1, j));
#pragma unroll
                for (int t = 0; t < NPAIR_A; t++) {
                    ffma2(Q0[t], fj[j][t], p0);
                    ffma2(Q1[t], fj[j][t], p1);
                }
            }
        }

#pragma unroll
        for (int t = 0; t < NPAIR_A; t++) {
            const float2 q0 = unpack2(Q0[t]), q1 = unpack2(Q1[t]);
            const int na = n0 + 2 * t, nb = na + 1;
            if (na < n_pts) {
                float* qrow = g_q + (size_t)na * CDIM;
                qrow[lane] = q0.x * scale; qrow[lane + 32] = q1.x * scale;
            }
            if (nb < n_pts) {
                float* qrow = g_q + (size_t)nb * CDIM;
                qrow[lane] = q0.y * scale; qrow[lane + 32] = q1.y * scale;
            }
        }
    }
}

// ---------------------------------------------------------------------------
// Kernel B: KNN gather attention + output projection (FFMA2 o-GEMM).
// ---------------------------------------------------------------------------
__global__ __launch_bounds__(WPB_B * 32) void attn_kernel(
    const int*   __restrict__ knn,
    const float* __restrict__ Wo,
    const float* __restrict__ bo,
    float*       __restrict__ out,
    int n_pts)
{
    __shared__ __align__(16) float W_t[CDIM * WSTRIDE];          // Wo
    __shared__ float bo_s[CDIM];
    __shared__ __align__(16) float2 fs2[WPB_B][NPAIR_B * CDIM];  // out vectors, pair-interleaved
    __shared__ __align__(16) float attnT[WPB_B][HEADS * TSTRIDE];

    const int tid = threadIdx.x;
    for (int i = tid; i < CDIM * CDIM; i += WPB_B * 32) {
        const int row = i >> 6, col = i & 63;
        W_t[col * WSTRIDE + row] = Wo[i];
    }
    if (tid < CDIM) bo_s[tid] = bo[tid];
    __syncthreads();

    const int wid  = tid >> 5;
    const int lane = tid & 31;
    const int n0 = (blockIdx.x * WPB_B + wid) * P_B;

    // per-lane constants
    const int r  = lane >> 3;           // k-gather: row slot 0..3
    const int e  = lane & 7;            // k-gather: head / 16B chunk
    const int hs = lane >> 2;           // softmax: head
    const int qt = lane & 3;            // softmax: quarter
    const int hv = lane >> 2;           // v-phase: head of channel pair `lane`

#pragma unroll
    for (int p = 0; p < P_B; p++) {
        const int n = n0 + p;
        if (n < n_pts) {
            int my_idx = 0;
            if (lane < KNN) my_idx = knn[(size_t)n * KNN + lane];

            // q for head e (channels 8e..8e+7), pre-scaled fp32 from scratch
            const float* qrow = g_q + (size_t)n * CDIM;
            const float4 qa = *reinterpret_cast<const float4*>(qrow + 8 * e);
            const float4 qb = *reinterpret_cast<const float4*>(qrow + 8 * e + 4);

            // ---- k gather: 4 x LDG.128, each covers 4 fp16 rows ----
            int ids[4];
#pragma unroll
            for (int i4 = 0; i4 < 4; i4++)
                ids[i4] = __shfl_sync(0xffffffffu, my_idx, 4 * i4 + r);
            uint4 raw[4];
#pragma unroll
            for (int i4 = 0; i4 < 4; i4++)
                raw[i4] = *reinterpret_cast<const uint4*>(
                    g_k16 + (size_t)ids[i4] * CDIM + e * 8);

#pragma unroll
            for (int i4 = 0; i4 < 4; i4++) {
                const float2 c0 = __half22float2(*reinterpret_cast<const __half2*>(&raw[i4].x));
                const float2 c1 = __half22float2(*reinterpret_cast<const __half2*>(&raw[i4].y));
                const float2 c2 = __half22float2(*reinterpret_cast<const __half2*>(&raw[i4].z));
                const float2 c3 = __half22float2(*reinterpret_cast<const __half2*>(&raw[i4].w));
                float acc = qa.x * c0.x;
                acc = fmaf(qa.y, c0.y, acc);
                acc = fmaf(qa.z, c1.x, acc);
                acc = fmaf(qa.w, c1.y, acc);
                acc = fmaf(qb.x, c2.x, acc);
                acc = fmaf(qb.y, c2.y, acc);
                acc = fmaf(qb.z, c3.x, acc);
                acc = fmaf(qb.w, c3.y, acc);
                attnT[wid][e * TSTRIDE + 4 * i4 + r] = acc;
            }
            __syncwarp();

            // ---- softmax: lane = (head hs, quarter qt); 4 scores per lane ----
            {
                float4 s4 = *reinterpret_cast<const float4*>(
                    &attnT[wid][hs * TSTRIDE + 4 * qt]);
                float m = fmaxf(fmaxf(s4.x, s4.y), fmaxf(s4.z, s4.w));
                m = fmaxf(m, __shfl_xor_sync(0xffffffffu, m, 1));
                m = fmaxf(m, __shfl_xor_sync(0xffffffffu, m, 2));
                const float e0 = __expf(s4.x - m);
                const float e1 = __expf(s4.y - m);
                const float e2 = __expf(s4.z - m);
                const float e3 = __expf(s4.w - m);
                float sum = (e0 + e1) + (e2 + e3);
                sum += __shfl_xor_sync(0xffffffffu, sum, 1);
                sum += __shfl_xor_sync(0xffffffffu, sum, 2);
                const float inv = __frcp_rn(sum);
                *reinterpret_cast<float4*>(&attnT[wid][hs * TSTRIDE + 4 * qt]) =
                    make_float4(e0 * inv, e1 * inv, e2 * inv, e3 * inv);
            }
            __syncwarp();

            // ---- out pair (2*lane, 2*lane+1) = sum_t attn[hv,t] * v[t,pair] ----
            float o0 = 0.f, o1 = 0.f;
#pragma unroll
            for (int tt = 0; tt < 4; tt++) {
                const float4 a = *reinterpret_cast<const float4*>(
                    &attnT[wid][hv * TSTRIDE + 4 * tt]);
#pragma unroll
                for (int u = 0; u < 4; u++) {
                    const int id = __shfl_sync(0xffffffffu, my_idx, 4 * tt + u);
                    const __half2 vh = reinterpret_cast<const __half2*>(
                        g_v16 + (size_t)id * CDIM)[lane];
                    const float2 vf = __half22float2(vh);
                    const float aw = f4_get(a, u);
                    o0 = fmaf(aw, vf.x, o0);
                    o1 = fmaf(aw, vf.y, o1);
                }
            }
            __syncwarp();   // done with attnT for this point
            // pair-interleaved store: channels 2*lane, 2*lane+1 of point p
            {
                float* dst = reinterpret_cast<float*>(&fs2[wid][(p >> 1) * CDIM]);
                dst[4 * lane + (p & 1)]     = o0;
                dst[4 * lane + 2 + (p & 1)] = o1;
            }
        }
        __syncwarp();       // attnT reuse across points
    }
    __syncwarp();

    // ---- final: y = outvec @ Wo + bo (packed FFMA2) ----
    uint64_t Y0[NPAIR_B], Y1[NPAIR_B];
#pragma unroll
    for (int t = 0; t < NPAIR_B; t++) {
        Y0[t] = pack2(bo_s[lane]);
        Y1[t] = pack2(bo_s[lane + 32]);
    }

    for (int i = 0; i < CDIM; i += 4) {
        uint64_t fj[4][NPAIR_B];
#pragma unroll
        for (int t = 0; t < NPAIR_B; t++) {
            const ulonglong2 fA = *reinterpret_cast<const ulonglong2*>(
                &fs2[wid][t * CDIM + i]);
            const ulonglong2 fB = *reinterpret_cast<const ulonglong2*>(
                &fs2[wid][t * CDIM + i + 2]);
            fj[0][t] = fA.x; fj[1][t] = fA.y; fj[2][t] = fB.x; fj[3][t] = fB.y;
        }
        const float4 w0 = *reinterpret_cast<const float4*>(&W_t[lane * WSTRIDE + i]);
        const float4 w1 = *reinterpret_cast<const float4*>(&W_t[(lane + 32) * WSTRIDE + i]);
#pragma unroll
        for (int j = 0; j < 4; j++) {
            const uint64_t p0 = pack2(f4_get(w0, j));
            const uint64_t p1 = pack2(f4_get(w1, j));
#pragma unroll
            for (int t = 0; t < NPAIR_B; t++) {
                ffma2(Y0[t], fj[j][t], p0);
                ffma2(Y1[t], fj[j][t], p1);
            }
        }
    }

#pragma unroll
    for (int t = 0; t < NPAIR_B; t++) {
        const float2 y0 = unpack2(Y0[t]), y1 = unpack2(Y1[t]);
        const int na = n0 + 2 * t, nb = na + 1;
        if (na < n_pts) {
            float* orow = out + (size_t)na * CDIM;
            orow[lane] = y0.x; orow[lane + 32] = y1.x;
        }
        if (nb < n_pts) {
            float* orow = out + (size_t)nb * CDIM;
            orow[lane] = y0.y; orow[lane + 32] = y1.y;
        }
    }
}

// ---------------------------------------------------------------------------
// Launch
// ---------------------------------------------------------------------------
extern "C" void kernel_launch(void* const* d_in, const int* in_sizes, int n_in,
                              void* d_out, int out_size)
{
    const float* feats = (const float*)d_in[0];
    const int*   knn   = (const int*)  d_in[1];
    const float* Wq    = (const float*)d_in[2];
    const float* Wk    = (const float*)d_in[3];
    const float* Wv    = (const float*)d_in[4];
    const float* Wo    = (const float*)d_in[5];
    const float* bo    = (const float*)d_in[6];
    float* out = (float*)d_out;

    const int n_pts = in_sizes[0] / CDIM;   // 100000

    const int ptsA = WPB_A * P_A;           // 32
    const int ptsB = WPB_B * P_B;           // 32
    const int gridA = (n_pts + ptsA - 1) / ptsA;
    const int gridB = (n_pts + ptsB - 1) / ptsB;

    proj_qkv_kernel<<<gridA, WPB_A * 32>>>(feats, Wq, Wk, Wv, n_pts);
    attn_kernel<<<gridB, WPB_B * 32>>>(knn, Wo, bo, out, n_pts);
}